// round 1
// baseline (speedup 1.0000x reference)
#include <cuda_runtime.h>
#include <cstddef>

#define TSTEPS 512
#define INDIM  22
#define HDIM   64
#define G4     256      // 4*H
#define KXP    24       // IN padded to multiple of 4
#define NTHR   256
#define NBLK   152
#define MMAX   28       // rows covered by compute (phantom rows padded with zeros)
#define BTOT   4096

// smem floats
#define SM_WX   (KXP*G4)       // 6144
#define SM_WH   (HDIM*G4)      // 16384
#define SM_BIAS (G4)           // 256
#define SM_XACT (MMAX*KXP)     // 672
#define SM_HACT (MMAX*HDIM)    // 1792
#define SM_GATE (MMAX*G4)      // 7168
#define SMEM_FLOATS (SM_WX + SM_WH + SM_BIAS + SM_XACT + SM_HACT + SM_GATE)
#define SMEM_BYTES  (SMEM_FLOATS * 4)

__device__ __forceinline__ float sigf(float x) {
    return __fdividef(1.0f, 1.0f + __expf(-x));
}
__device__ __forceinline__ float tanh_fast(float x) {
    return __fdividef(2.0f, 1.0f + __expf(-2.0f * x)) - 1.0f;
}

// acc[j] += a.{x,y,z,w} dot w{0..3}[j]  (4 k-steps, 4 gate columns)
__device__ __forceinline__ void fma16(float* acc, float4 a,
                                      float4 w0, float4 w1, float4 w2, float4 w3) {
    acc[0] = fmaf(a.x, w0.x, acc[0]);
    acc[1] = fmaf(a.x, w0.y, acc[1]);
    acc[2] = fmaf(a.x, w0.z, acc[2]);
    acc[3] = fmaf(a.x, w0.w, acc[3]);
    acc[0] = fmaf(a.y, w1.x, acc[0]);
    acc[1] = fmaf(a.y, w1.y, acc[1]);
    acc[2] = fmaf(a.y, w1.z, acc[2]);
    acc[3] = fmaf(a.y, w1.w, acc[3]);
    acc[0] = fmaf(a.z, w2.x, acc[0]);
    acc[1] = fmaf(a.z, w2.y, acc[1]);
    acc[2] = fmaf(a.z, w2.z, acc[2]);
    acc[3] = fmaf(a.z, w2.w, acc[3]);
    acc[0] = fmaf(a.w, w3.x, acc[0]);
    acc[1] = fmaf(a.w, w3.y, acc[1]);
    acc[2] = fmaf(a.w, w3.z, acc[2]);
    acc[3] = fmaf(a.w, w3.w, acc[3]);
}

__global__ __launch_bounds__(NTHR, 1)
void lstm_persistent_kernel(const float* __restrict__ in,
                            const float* __restrict__ Wih,
                            const float* __restrict__ Whh,
                            const float* __restrict__ bih,
                            const float* __restrict__ bhh,
                            float* __restrict__ out)
{
    extern __shared__ float sm[];
    float* Wx    = sm;                   // [KXP][G4]   k-major
    float* Wh    = Wx + SM_WX;           // [HDIM][G4]  k-major
    float* bias  = Wh + SM_WH;           // [G4]
    float* xact  = bias + SM_BIAS;       // [MMAX][KXP]
    float* hact  = xact + SM_XACT;       // [MMAX][HDIM]
    float* gates = hact + SM_HACT;       // [MMAX][G4]

    const int tid = threadIdx.x;
    const int bid = blockIdx.x;

    // 4096 = 152*26 + 144 -> first 144 blocks get 27 rows, last 8 get 26
    const int M        = (bid < 144) ? 27 : 26;
    const int rowStart = (bid < 144) ? bid * 27 : 144 * 27 + (bid - 144) * 26;

    // ---- prologue: zero padded regions ----
    for (int i = tid; i < SM_WX;   i += NTHR) Wx[i]   = 0.0f;
    for (int i = tid; i < SM_XACT; i += NTHR) xact[i] = 0.0f;
    for (int i = tid; i < SM_HACT; i += NTHR) hact[i] = 0.0f;
    __syncthreads();

    // weights transposed into k-major smem (one-time)
    for (int i = tid; i < G4 * INDIM; i += NTHR) {
        int g = i / INDIM, k = i - g * INDIM;
        Wx[k * G4 + g] = Wih[i];
    }
    for (int i = tid; i < G4 * HDIM; i += NTHR) {
        int g = i >> 6, k = i & 63;
        Wh[k * G4 + g] = Whh[i];
    }
    for (int i = tid; i < G4; i += NTHR) bias[i] = bih[i] + bhh[i];

    // ---- x prefetch slots (each thread owns up to 3 scalars of the x tile) ----
    const int NXL = 3;
    const float* xp[NXL];
    int  sx[NXL];
    bool xv[NXL];
#pragma unroll
    for (int q = 0; q < NXL; q++) {
        int idx = tid + q * NTHR;
        xv[q] = (idx < M * INDIM);
        int r  = idx / INDIM;
        int i2 = idx - r * INDIM;
        sx[q] = r * KXP + i2;
        xp[q] = xv[q] ? (in + (size_t)(rowStart + r) * TSTEPS * INDIM + i2) : in;
    }

    // ---- gate-compute mapping: 4 gate cols x 7 rows per thread ----
    const int tx  = tid & 63;
    const int ty  = tid >> 6;
    const int g04 = tx;        // float4 column index (gate cols tx*4..tx*4+3)
    const int r0  = ty * 7;

    // ---- pointwise mapping: 8 threads per row, 8 h-units each ----
    const int tr = tid >> 3;           // 0..31 (active if < MMAX)
    const int jb = (tid & 7) * 8;
    float* outp = out + (size_t)(rowStart + tr) * TSTEPS * HDIM + jb;
    float c[8];
#pragma unroll
    for (int j = 0; j < 8; j++) c[j] = 0.0f;

    const float4* Wx4   = (const float4*)Wx;
    const float4* Wh4   = (const float4*)Wh;
    const float4* xact4 = (const float4*)xact;
    const float4* hact4 = (const float4*)hact;

    __syncthreads();

    // load x(t=0)
#pragma unroll
    for (int q = 0; q < NXL; q++)
        if (xv[q]) xact[sx[q]] = xp[q][0];

    const float4 b4 = ((const float4*)bias)[g04];
    __syncthreads();

    // ================= main recurrence =================
    for (int t = 0; t < TSTEPS; t++) {
        // prefetch x(t+1) into registers (consumed at end of step)
        float xr[NXL];
        if (t + 1 < TSTEPS) {
#pragma unroll
            for (int q = 0; q < NXL; q++)
                xr[q] = xv[q] ? xp[q][(size_t)(t + 1) * INDIM] : 0.0f;
        }

        // ---- gates = bias + x W_ih^T + h W_hh^T ----
        float acc[7][4];
#pragma unroll
        for (int r = 0; r < 7; r++) {
            acc[r][0] = b4.x; acc[r][1] = b4.y; acc[r][2] = b4.z; acc[r][3] = b4.w;
        }

#pragma unroll 2
        for (int kk = 0; kk < KXP / 4; kk++) {
            float4 w0 = Wx4[(kk * 4 + 0) * 64 + g04];
            float4 w1 = Wx4[(kk * 4 + 1) * 64 + g04];
            float4 w2 = Wx4[(kk * 4 + 2) * 64 + g04];
            float4 w3 = Wx4[(kk * 4 + 3) * 64 + g04];
#pragma unroll
            for (int r = 0; r < 7; r++) {
                float4 a = xact4[(r0 + r) * (KXP / 4) + kk];   // warp-broadcast
                fma16(acc[r], a, w0, w1, w2, w3);
            }
        }

#pragma unroll 2
        for (int kk = 0; kk < HDIM / 4; kk++) {
            float4 w0 = Wh4[(kk * 4 + 0) * 64 + g04];
            float4 w1 = Wh4[(kk * 4 + 1) * 64 + g04];
            float4 w2 = Wh4[(kk * 4 + 2) * 64 + g04];
            float4 w3 = Wh4[(kk * 4 + 3) * 64 + g04];
#pragma unroll
            for (int r = 0; r < 7; r++) {
                float4 a = hact4[(r0 + r) * (HDIM / 4) + kk];  // warp-broadcast
                fma16(acc[r], a, w0, w1, w2, w3);
            }
        }

#pragma unroll
        for (int r = 0; r < 7; r++) {
            float4 v = make_float4(acc[r][0], acc[r][1], acc[r][2], acc[r][3]);
            ((float4*)&gates[(r0 + r) * G4])[g04] = v;
        }
        __syncthreads();

        // ---- pointwise LSTM cell ----
        if (tr < MMAX) {
            const float4* grow = (const float4*)&gates[tr * G4];
            float vi[8], vf[8], vg[8], vo[8], hv[8];
            const int j4 = jb >> 2;
            *(float4*)&vi[0] = grow[j4];          *(float4*)&vi[4] = grow[j4 + 1];
            *(float4*)&vf[0] = grow[16 + j4];     *(float4*)&vf[4] = grow[16 + j4 + 1];
            *(float4*)&vg[0] = grow[32 + j4];     *(float4*)&vg[4] = grow[32 + j4 + 1];
            *(float4*)&vo[0] = grow[48 + j4];     *(float4*)&vo[4] = grow[48 + j4 + 1];
#pragma unroll
            for (int j = 0; j < 8; j++) {
                float ig = sigf(vi[j]);
                float fg = sigf(vf[j]);
                float gg = tanh_fast(vg[j]);
                float og = sigf(vo[j]);
                float cn = fmaf(fg, c[j], ig * gg);
                c[j] = cn;
                hv[j] = og * tanh_fast(cn);
            }
            float4* hrow = (float4*)&hact[tr * HDIM];
            hrow[j4]     = *(float4*)&hv[0];
            hrow[j4 + 1] = *(float4*)&hv[4];
            if (tr < M) {
                *(float4*)(outp + (size_t)t * HDIM)     = *(float4*)&hv[0];
                *(float4*)(outp + (size_t)t * HDIM + 4) = *(float4*)&hv[4];
            }
        }

        // publish x(t+1) into smem for next step
        if (t + 1 < TSTEPS) {
#pragma unroll
            for (int q = 0; q < NXL; q++)
                if (xv[q]) xact[sx[q]] = xr[q];
        }
        __syncthreads();
    }
}

extern "C" void kernel_launch(void* const* d_in, const int* in_sizes, int n_in,
                              void* d_out, int out_size)
{
    const float* in  = (const float*)d_in[0];
    const float* Wih = (const float*)d_in[1];
    const float* Whh = (const float*)d_in[2];
    const float* bih = (const float*)d_in[3];
    const float* bhh = (const float*)d_in[4];
    float* out = (float*)d_out;

    cudaFuncSetAttribute(lstm_persistent_kernel,
                         cudaFuncAttributeMaxDynamicSharedMemorySize, SMEM_BYTES);

    lstm_persistent_kernel<<<NBLK, NTHR, SMEM_BYTES>>>(in, Wih, Whh, bih, bhh, out);
}